// round 4
// baseline (speedup 1.0000x reference)
#include <cuda_runtime.h>
#include <cuda_bf16.h>
#include <math.h>

// Problem constants
#define V_  100000
#define D_  128
#define A_  64
#define L_  3
#define N_  20000
#define K_  16

typedef unsigned long long ull;

// Device scratch (no allocation allowed anywhere). 256B-aligned: these are
// accessed through float4 casts, and __device__ float arrays only guarantee
// 4B alignment by themselves.
__device__ __align__(256) float g_E [(size_t)V_ * A_];   // W_tmp @ W_bot (running)
__device__ __align__(256) float g_NT[(size_t)V_ * A_];   // Leaf_emb @ W_top (fixed)
__device__ __align__(256) float g_temp[(size_t)N_ * D_]; // per-level temp_emb
__device__ int   g_win[(size_t)L_ * V_];  // per-level last-wins winner n (or -1)
__device__ int   g_count[4];              // compacted winner counts per level
__device__ int   g_list[L_ * N_];         // compacted winner n-indices per level

// ---------------- f32x2 packed-FMA helpers (sm_103a FFMA2) -----------------
__device__ __forceinline__ ull pack2(float x, float y) {
    ull r; asm("mov.b64 %0, {%1,%2};" : "=l"(r) : "f"(x), "f"(y)); return r;
}
__device__ __forceinline__ void unpack2(ull v, float& x, float& y) {
    asm("mov.b64 {%0,%1}, %2;" : "=f"(x), "=f"(y) : "l"(v));
}
__device__ __forceinline__ ull fma2(ull a, ull b, ull c) {
    ull d; asm("fma.rn.f32x2 %0, %1, %2, %3;" : "=l"(d) : "l"(a), "l"(b), "l"(c));
    return d;
}

// ---------------------------------------------------------------------------
// init: winners = -1 for all levels, counts = 0 (runs every replay)
// ---------------------------------------------------------------------------
__global__ void init_kernel() {
    int i = blockIdx.x * blockDim.x + threadIdx.x;
    if (i < L_ * V_) g_win[i] = -1;
    if (i < 4)       g_count[i] = 0;
}

// ---------------------------------------------------------------------------
// winners: g_win[l][node] = max n with nodes[l][n] == node  (last-wins)
// ---------------------------------------------------------------------------
__global__ void win_kernel(const int* __restrict__ nodes) {
    int i = blockIdx.x * blockDim.x + threadIdx.x;
    if (i >= L_ * N_) return;
    int l = i / N_;
    int n = i - l * N_;
    atomicMax(&g_win[(size_t)l * V_ + nodes[i]], n);
}

// ---------------------------------------------------------------------------
// lists: compact winner n's per level (order nondeterministic; each winner
// targets a distinct node so final output stays deterministic)
// ---------------------------------------------------------------------------
__global__ void list_kernel(const int* __restrict__ nodes) {
    int i = blockIdx.x * blockDim.x + threadIdx.x;
    if (i >= L_ * N_) return;
    int l = i / N_;
    int n = i - l * N_;
    if (g_win[(size_t)l * V_ + nodes[i]] == n) {
        int pos = atomicAdd(&g_count[l], 1);
        g_list[l * N_ + pos] = n;
    }
}

// ---------------------------------------------------------------------------
// proj: NT[v] = emb[v]@W_top, E[v] = emb[v]@W_bot, Wtmp[v] = emb[v].
// 256 threads, 16 rows/block (grid = 6250 exact). Dynamic smem:
//   sW  float[128][128]  concatenated (top|bottom) columns  = 64KB
//   sT  float[128][20]   transposed emb (stride 20 floats = 80B, 16B-multiple)
//   sL  float[16][128]   linear staging for emb
// thread: out-col = tid&127, row-group rg = tid>>7 (8 rows), f32x2 row pairs.
// ---------------------------------------------------------------------------
__global__ void proj_kernel(const float* __restrict__ emb,
                            const float* __restrict__ W_att,
                            float* __restrict__ Wtmp) {
    extern __shared__ __align__(16) float sm[];
    float* sW = sm;                       // 16384
    float* sT = sm + 16384;               // 128*20 = 2560 (base 64KB: 16B aligned)
    float* sL = sm + 16384 + 2560;        // 2048 (byte offset 75776: 16B aligned)

    const int tid = threadIdx.x;
    const int v0  = blockIdx.x * 16;

    // stage concatenated W
    for (int i = tid; i < 16384; i += 256) {
        int d = i >> 7, o = i & 127;
        sW[i] = (o < 64) ? W_att[d * 64 + o] : W_att[(128 + d) * 64 + (o - 64)];
    }
    // stage emb linear + fused Wtmp init
    {
        const float4* src = reinterpret_cast<const float4*>(emb + (size_t)v0 * 128);
        float4* dst = reinterpret_cast<float4*>(Wtmp + (size_t)v0 * 128);
        float4* sl4 = reinterpret_cast<float4*>(sL);
#pragma unroll
        for (int i = tid; i < 512; i += 256) {
            float4 v = src[i];
            dst[i] = v;
            sl4[i] = v;
        }
    }
    __syncthreads();
    // transpose into sT (stride 20 floats = 80 bytes; 80 % 16 == 0)
    for (int i = tid; i < 2048; i += 256) {
        int r = i >> 7, d = i & 127;
        sT[d * 20 + r] = sL[i];
    }
    __syncthreads();

    const int out = tid & 127;
    const int rg  = tid >> 7;
    const float* base = sT + rg * 8;     // +0 or +32 bytes: 16B-multiple
    ull acc0 = 0, acc1 = 0, acc2 = 0, acc3 = 0;

#pragma unroll 4
    for (int d = 0; d < 128; d++) {
        float w = sW[d * 128 + out];
        ull w2 = pack2(w, w);
        double2 eA = *reinterpret_cast<const double2*>(base + d * 20);      // rows 0-3
        double2 eB = *reinterpret_cast<const double2*>(base + d * 20 + 4);  // rows 4-7
        acc0 = fma2(__double_as_longlong(eA.x), w2, acc0);
        acc1 = fma2(__double_as_longlong(eA.y), w2, acc1);
        acc2 = fma2(__double_as_longlong(eB.x), w2, acc2);
        acc3 = fma2(__double_as_longlong(eB.y), w2, acc3);
    }

    const bool top = (out < 64);
    float* dstbuf = top ? g_NT : g_E;
    const int oo = top ? out : out - 64;
    ull accs[4] = {acc0, acc1, acc2, acc3};
#pragma unroll
    for (int p = 0; p < 4; p++) {
        float x, y; unpack2(accs[p], x, y);
        size_t v = (size_t)(v0 + rg * 8 + 2 * p);
        dstbuf[v * 64 + oo]       = x;
        dstbuf[(v + 1) * 64 + oo] = y;
    }
}

// ---------------------------------------------------------------------------
// attention: one block (128 threads) per node n. Wtmp gather overlapped with
// the E-gather/MLP phase; masks/weights prefetched at start.
// ---------------------------------------------------------------------------
__global__ void attn_kernel(const float* __restrict__ Wtmp,
                            const int*   __restrict__ nodes,
                            const int*   __restrict__ neighbors,
                            const float* __restrict__ masks,
                            const float* __restrict__ weights,
                            const float* __restrict__ b_att,
                            const float* __restrict__ v_att,
                            int level) {
    int n = blockIdx.x;
    int tid = threadIdx.x;
    size_t base = (size_t)level * N_ + n;

    __shared__ int s_node;
    __shared__ __align__(16) int   s_neigh[K_];
    __shared__ float s_pre[K_];
    __shared__ float s_att[K_];

    // early prefetch of softmax inputs (warp 0 registers)
    float mval = -INFINITY, wval = -INFINITY;
    if (tid < K_) {
        mval = masks[base * K_ + tid];
        wval = weights[base * K_ + tid];
    }
    if (tid < 4)
        reinterpret_cast<int4*>(s_neigh)[tid] =
            reinterpret_cast<const int4*>(neighbors + base * K_)[tid];
    if (tid == 64) s_node = nodes[base];
    __syncthreads();
    int node = s_node;

    // ---- phase 1 loads: E[neigh_k] / NT[node]; tid -> (k = tid>>3, g = tid&7)
    int k = tid >> 3;
    int g = tid & 7;
    int neigh = s_neigh[k];
    const float4* E4  = reinterpret_cast<const float4*>(&g_E [(size_t)neigh * A_]);
    const float4* NT4 = reinterpret_cast<const float4*>(&g_NT[(size_t)node  * A_]);
    const float4* b4  = reinterpret_cast<const float4*>(b_att);
    const float4* v4  = reinterpret_cast<const float4*>(v_att);
    float4 e0  = E4[g * 2],     e1  = E4[g * 2 + 1];
    float4 nt0 = NT4[g * 2],    nt1 = NT4[g * 2 + 1];
    float4 bb0 = b4[g * 2],     bb1 = b4[g * 2 + 1];
    float4 vv0 = v4[g * 2],     vv1 = v4[g * 2 + 1];

    // ---- phase 3 gather (overlapped): Wtmp[neigh_k][d=tid] into registers
    float wv[K_];
#pragma unroll
    for (int kk = 0; kk < K_; kk++)
        wv[kk] = Wtmp[(size_t)s_neigh[kk] * D_ + tid];

    // ---- phase 1 compute
    float psum;
    {
        float z0 = nt0.x + e0.x + bb0.x; z0 = z0 > 0.f ? z0 : 0.01f * z0;
        float z1 = nt0.y + e0.y + bb0.y; z1 = z1 > 0.f ? z1 : 0.01f * z1;
        float z2 = nt0.z + e0.z + bb0.z; z2 = z2 > 0.f ? z2 : 0.01f * z2;
        float z3 = nt0.w + e0.w + bb0.w; z3 = z3 > 0.f ? z3 : 0.01f * z3;
        psum  = vv0.x * z0;
        psum = fmaf(vv0.y, z1, psum);
        psum = fmaf(vv0.z, z2, psum);
        psum = fmaf(vv0.w, z3, psum);
        z0 = nt1.x + e1.x + bb1.x; z0 = z0 > 0.f ? z0 : 0.01f * z0;
        z1 = nt1.y + e1.y + bb1.y; z1 = z1 > 0.f ? z1 : 0.01f * z1;
        z2 = nt1.z + e1.z + bb1.z; z2 = z2 > 0.f ? z2 : 0.01f * z2;
        z3 = nt1.w + e1.w + bb1.w; z3 = z3 > 0.f ? z3 : 0.01f * z3;
        psum = fmaf(vv1.x, z0, psum);
        psum = fmaf(vv1.y, z1, psum);
        psum = fmaf(vv1.z, z2, psum);
        psum = fmaf(vv1.w, z3, psum);
    }
#pragma unroll
    for (int off = 4; off; off >>= 1)
        psum += __shfl_down_sync(0xffffffffu, psum, off);
    if (g == 0) s_pre[k] = psum;
    __syncthreads();

    // ---- phase 2: dual softmax on warp 0
    if (tid < 32) {
        float pre = (tid < K_) ? s_pre[tid] + mval : -INFINITY;
        float w   = wval;
        float m1 = pre, m2 = w;
#pragma unroll
        for (int off = 8; off; off >>= 1) {
            m1 = fmaxf(m1, __shfl_xor_sync(0xffffffffu, m1, off));
            m2 = fmaxf(m2, __shfl_xor_sync(0xffffffffu, m2, off));
        }
        float e1v = (tid < K_) ? __expf(pre - m1) : 0.f;
        float e2v = (tid < K_) ? __expf(w   - m2) : 0.f;
        float s1 = e1v, s2 = e2v;
#pragma unroll
        for (int off = 8; off; off >>= 1) {
            s1 += __shfl_xor_sync(0xffffffffu, s1, off);
            s2 += __shfl_xor_sync(0xffffffffu, s2, off);
        }
        if (tid < K_) s_att[tid] = (e1v / s1) * (e2v / s2);
    }
    __syncthreads();

    // ---- phase 3 reduce from registers
    float acc = 0.f;
#pragma unroll
    for (int kk = 0; kk < K_; kk++)
        acc = fmaf(s_att[kk], wv[kk], acc);
    g_temp[(size_t)n * D_ + tid] = acc;
}

// ---------------------------------------------------------------------------
// scatterE (levels 0,1): over compact winner list — write Wtmp row AND
// recompute g_E row. 16 winners / 256-thread block, grid = 1250, early exit.
// ---------------------------------------------------------------------------
__global__ void scatterE_kernel(float* __restrict__ Wtmp,
                                const int* __restrict__ nodes,
                                const float* __restrict__ W_att,
                                int level) {
    __shared__ __align__(16) float sWb[128 * 64];
    __shared__ __align__(16) float s_t[16 * 128];
    __shared__ int   s_n[16];
    __shared__ int   s_nd[16];

    int cnt = g_count[level];
    int base = blockIdx.x * 16;
    if (base >= cnt) return;
    int tid = threadIdx.x;

    for (int i = tid; i < 128 * 64; i += 256) {
        int d = i >> 6, a = i & 63;
        sWb[i] = W_att[(128 + d) * 64 + a];
    }
    if (tid < 16) {
        int item = base + tid;
        int nn = (item < cnt) ? g_list[level * N_ + item] : -1;
        s_n[tid]  = nn;
        s_nd[tid] = (nn >= 0) ? nodes[(size_t)level * N_ + nn] : -1;
    }
    __syncthreads();
    // stage temp rows + fused Wtmp row write (float4)
    for (int i = tid; i < 512; i += 256) {
        int r = i >> 5, q = i & 31;
        int nn = s_n[r];
        float4 v = (nn >= 0)
            ? reinterpret_cast<const float4*>(g_temp + (size_t)nn * 128)[q]
            : make_float4(0.f, 0.f, 0.f, 0.f);
        reinterpret_cast<float4*>(s_t + r * 128)[q] = v;
        if (nn >= 0)
            reinterpret_cast<float4*>(Wtmp + (size_t)s_nd[r] * 128)[q] = v;
    }
    __syncthreads();

    int a  = tid & 63;
    int rg = tid >> 6;
    float acc[4] = {0.f, 0.f, 0.f, 0.f};
    const float* tr = s_t + (rg * 4) * 128;
#pragma unroll 4
    for (int d = 0; d < 128; d++) {
        float w = sWb[d * 64 + a];
        acc[0] = fmaf(tr[d],       w, acc[0]);
        acc[1] = fmaf(tr[128 + d], w, acc[1]);
        acc[2] = fmaf(tr[256 + d], w, acc[2]);
        acc[3] = fmaf(tr[384 + d], w, acc[3]);
    }
#pragma unroll
    for (int r = 0; r < 4; r++) {
        int nn = s_n[rg * 4 + r];
        if (nn >= 0)
            g_E[(size_t)s_nd[rg * 4 + r] * A_ + a] = acc[r];
    }
}

// ---------------------------------------------------------------------------
// scatter_copy (last level): row copy only, over compact list.
// 8 winners / 256-thread block (one warp each, float4 lanes). grid = 2500.
// ---------------------------------------------------------------------------
__global__ void scatter_copy_kernel(float* __restrict__ Wtmp,
                                    const int* __restrict__ nodes,
                                    int level) {
    int grp  = threadIdx.x >> 5;
    int lane = threadIdx.x & 31;
    int item = blockIdx.x * 8 + grp;
    if (item >= g_count[level]) return;
    int nn   = g_list[level * N_ + item];
    int node = nodes[(size_t)level * N_ + nn];
    reinterpret_cast<float4*>(Wtmp + (size_t)node * 128)[lane] =
        reinterpret_cast<const float4*>(g_temp + (size_t)nn * 128)[lane];
}

// ---------------------------------------------------------------------------
extern "C" void kernel_launch(void* const* d_in, const int* in_sizes, int n_in,
                              void* d_out, int out_size) {
    const float* Leaf_emb  = (const float*)d_in[0];
    const int*   nodes     = (const int*)  d_in[1];
    const int*   neighbors = (const int*)  d_in[2];
    const float* masks     = (const float*)d_in[3];
    const float* weights   = (const float*)d_in[4];
    const float* W_att     = (const float*)d_in[5];
    const float* b_att     = (const float*)d_in[6];
    const float* v_att     = (const float*)d_in[7];
    float* Wtmp = (float*)d_out;

    const int proj_smem = (16384 + 2560 + 2048) * (int)sizeof(float); // 84KB

    static bool attr_done = false;
    if (!attr_done) {
        cudaFuncSetAttribute(proj_kernel,
                             cudaFuncAttributeMaxDynamicSharedMemorySize,
                             proj_smem);
        attr_done = true;
    }

    init_kernel<<<(L_ * V_ + 255) / 256, 256>>>();
    win_kernel <<<(L_ * N_ + 255) / 256, 256>>>(nodes);
    list_kernel<<<(L_ * N_ + 255) / 256, 256>>>(nodes);

    proj_kernel<<<V_ / 16, 256, proj_smem>>>(Leaf_emb, W_att, Wtmp);

    for (int lvl = 0; lvl < L_; lvl++) {
        attn_kernel<<<N_, 128>>>(Wtmp, nodes, neighbors, masks, weights,
                                 b_att, v_att, lvl);
        if (lvl < L_ - 1)
            scatterE_kernel<<<(N_ + 15) / 16, 256>>>(Wtmp, nodes, W_att, lvl);
        else
            scatter_copy_kernel<<<(N_ + 7) / 8, 256>>>(Wtmp, nodes, lvl);
    }
}

// round 5
// speedup vs baseline: 1.4016x; 1.4016x over previous
#include <cuda_runtime.h>
#include <cuda_bf16.h>
#include <math.h>

// Problem constants
#define V_  100000
#define D_  128
#define A_  64
#define L_  3
#define N_  20000
#define K_  16

typedef unsigned long long ull;

// Device scratch. 256B-aligned: accessed through float4 casts.
__device__ __align__(256) float g_E [(size_t)V_ * A_];   // W_tmp @ W_bot (running)
__device__ __align__(256) float g_NT[(size_t)V_ * A_];   // Leaf_emb @ W_top (fixed)
__device__ __align__(256) float g_temp[(size_t)N_ * D_]; // per-level temp_emb
__device__ int   g_win[(size_t)L_ * V_];  // per-level last-wins winner n (or -1)
__device__ int   g_count[4];              // compacted winner counts per level
__device__ int   g_list[L_ * N_];         // compacted winner n-indices per level

// ---------------- f32x2 packed-FMA helpers (sm_103a FFMA2) -----------------
__device__ __forceinline__ ull pack2(float x, float y) {
    ull r; asm("mov.b64 %0, {%1,%2};" : "=l"(r) : "f"(x), "f"(y)); return r;
}
__device__ __forceinline__ void unpack2(ull v, float& x, float& y) {
    asm("mov.b64 {%0,%1}, %2;" : "=f"(x), "=f"(y) : "l"(v));
}
__device__ __forceinline__ ull fma2(ull a, ull b, ull c) {
    ull d; asm("fma.rn.f32x2 %0, %1, %2, %3;" : "=l"(d) : "l"(a), "l"(b), "l"(c));
    return d;
}

// ---------------------------------------------------------------------------
// init: winners = -1 for all levels, counts = 0 (runs every replay)
// ---------------------------------------------------------------------------
__global__ void init_kernel() {
    int i = blockIdx.x * blockDim.x + threadIdx.x;
    if (i < L_ * V_) g_win[i] = -1;
    if (i < 4)       g_count[i] = 0;
}

// ---------------------------------------------------------------------------
// winners: g_win[l][node] = max n with nodes[l][n] == node  (last-wins)
// ---------------------------------------------------------------------------
__global__ void win_kernel(const int* __restrict__ nodes) {
    int i = blockIdx.x * blockDim.x + threadIdx.x;
    if (i >= L_ * N_) return;
    int l = i / N_;
    int n = i - l * N_;
    atomicMax(&g_win[(size_t)l * V_ + nodes[i]], n);
}

// ---------------------------------------------------------------------------
// lists: compact winner n's per level (order nondeterministic; each winner
// targets a distinct node so final output stays deterministic)
// ---------------------------------------------------------------------------
__global__ void list_kernel(const int* __restrict__ nodes) {
    int i = blockIdx.x * blockDim.x + threadIdx.x;
    if (i >= L_ * N_) return;
    int l = i / N_;
    int n = i - l * N_;
    if (g_win[(size_t)l * V_ + nodes[i]] == n) {
        int pos = atomicAdd(&g_count[l], 1);
        g_list[l * N_ + pos] = n;
    }
}

// ---------------------------------------------------------------------------
// proj: NT[v] = emb[v]@W_top, E[v] = emb[v]@W_bot, Wtmp[v] = emb[v].
// 256 threads, 32 rows/block (grid = 3125 exact). No smem W tile: W is 64KB,
// shared by every block -> L1-resident, read via coalesced LDG.64.
// smem: sT transposed emb [128 d][36 stride] + sL linear staging = 34KB.
// Thread: 2 adjacent outs (op = tid&63) x 8 rows (rg = tid>>6), f32x2 accs.
// ---------------------------------------------------------------------------
__global__ __launch_bounds__(256, 3)
void proj_kernel(const float* __restrict__ emb,
                 const float* __restrict__ W_att,
                 float* __restrict__ Wtmp) {
    __shared__ __align__(16) float sT[128 * 36];
    __shared__ __align__(16) float sL[32 * 128];

    const int tid = threadIdx.x;
    const int v0  = blockIdx.x * 32;

    // stage emb rows (float4) + fused Wtmp init
    {
        const float4* src = reinterpret_cast<const float4*>(emb + (size_t)v0 * 128);
        float4* dst = reinterpret_cast<float4*>(Wtmp + (size_t)v0 * 128);
        float4* sl4 = reinterpret_cast<float4*>(sL);
#pragma unroll
        for (int i = tid; i < 32 * 32; i += 256) {
            float4 v = src[i];
            dst[i] = v;
            sl4[i] = v;
        }
    }
    __syncthreads();
    // transpose: sT[d][r] = sL[r][d]  (stride 36 floats = 144B, 16B-multiple)
    for (int i = tid; i < 32 * 128; i += 256) {
        int r = i >> 7, d = i & 127;
        sT[d * 36 + r] = sL[i];
    }
    __syncthreads();

    const int op = tid & 63;            // outs {2op, 2op+1}
    const int rg = tid >> 6;            // rows rg*8 .. rg*8+7
    const int o  = 2 * op;
    const float* wbase = W_att + (o < 64 ? o : 8192 + (o - 64));
    const float* tbase = sT + rg * 8;

    ull a00 = 0, a01 = 0, a02 = 0, a03 = 0;   // out o,   row pairs
    ull a10 = 0, a11 = 0, a12 = 0, a13 = 0;   // out o+1, row pairs

#pragma unroll 4
    for (int d = 0; d < 128; d++) {
        float2 w = *reinterpret_cast<const float2*>(wbase + d * 64);
        const float* tp = tbase + d * 36;
        double2 eA = *reinterpret_cast<const double2*>(tp);      // rows 0-3
        double2 eB = *reinterpret_cast<const double2*>(tp + 4);  // rows 4-7
        ull w0 = pack2(w.x, w.x);
        ull w1 = pack2(w.y, w.y);
        ull e0 = __double_as_longlong(eA.x);
        ull e1 = __double_as_longlong(eA.y);
        ull e2 = __double_as_longlong(eB.x);
        ull e3 = __double_as_longlong(eB.y);
        a00 = fma2(e0, w0, a00);  a10 = fma2(e0, w1, a10);
        a01 = fma2(e1, w0, a01);  a11 = fma2(e1, w1, a11);
        a02 = fma2(e2, w0, a02);  a12 = fma2(e2, w1, a12);
        a03 = fma2(e3, w0, a03);  a13 = fma2(e3, w1, a13);
    }

    float* buf = (o < 64) ? g_NT : g_E;
    const int oo = (o < 64) ? o : o - 64;
    ull aA[4] = {a00, a01, a02, a03};
    ull aB[4] = {a10, a11, a12, a13};
#pragma unroll
    for (int p = 0; p < 4; p++) {
        float x0, y0, x1, y1;
        unpack2(aA[p], x0, y0);   // out o,   rows 2p / 2p+1
        unpack2(aB[p], x1, y1);   // out o+1, rows 2p / 2p+1
        size_t r0 = (size_t)(v0 + rg * 8 + 2 * p);
        *reinterpret_cast<float2*>(buf + r0 * 64 + oo)       = make_float2(x0, x1);
        *reinterpret_cast<float2*>(buf + (r0 + 1) * 64 + oo) = make_float2(y0, y1);
    }
}

// ---------------------------------------------------------------------------
// attention: one block (128 threads) per node n. Wtmp gather overlapped with
// the E-gather/MLP phase; masks/weights prefetched at start.
// ---------------------------------------------------------------------------
__global__ void attn_kernel(const float* __restrict__ Wtmp,
                            const int*   __restrict__ nodes,
                            const int*   __restrict__ neighbors,
                            const float* __restrict__ masks,
                            const float* __restrict__ weights,
                            const float* __restrict__ b_att,
                            const float* __restrict__ v_att,
                            int level) {
    int n = blockIdx.x;
    int tid = threadIdx.x;
    size_t base = (size_t)level * N_ + n;

    __shared__ int s_node;
    __shared__ __align__(16) int   s_neigh[K_];
    __shared__ float s_pre[K_];
    __shared__ float s_att[K_];

    float mval = -INFINITY, wval = -INFINITY;
    if (tid < K_) {
        mval = masks[base * K_ + tid];
        wval = weights[base * K_ + tid];
    }
    if (tid < 4)
        reinterpret_cast<int4*>(s_neigh)[tid] =
            reinterpret_cast<const int4*>(neighbors + base * K_)[tid];
    if (tid == 64) s_node = nodes[base];
    __syncthreads();
    int node = s_node;

    int k = tid >> 3;
    int g = tid & 7;
    int neigh = s_neigh[k];
    const float4* E4  = reinterpret_cast<const float4*>(&g_E [(size_t)neigh * A_]);
    const float4* NT4 = reinterpret_cast<const float4*>(&g_NT[(size_t)node  * A_]);
    const float4* b4  = reinterpret_cast<const float4*>(b_att);
    const float4* v4  = reinterpret_cast<const float4*>(v_att);
    float4 e0  = E4[g * 2],     e1  = E4[g * 2 + 1];
    float4 nt0 = NT4[g * 2],    nt1 = NT4[g * 2 + 1];
    float4 bb0 = b4[g * 2],     bb1 = b4[g * 2 + 1];
    float4 vv0 = v4[g * 2],     vv1 = v4[g * 2 + 1];

    float wv[K_];
#pragma unroll
    for (int kk = 0; kk < K_; kk++)
        wv[kk] = Wtmp[(size_t)s_neigh[kk] * D_ + tid];

    float psum;
    {
        float z0 = nt0.x + e0.x + bb0.x; z0 = z0 > 0.f ? z0 : 0.01f * z0;
        float z1 = nt0.y + e0.y + bb0.y; z1 = z1 > 0.f ? z1 : 0.01f * z1;
        float z2 = nt0.z + e0.z + bb0.z; z2 = z2 > 0.f ? z2 : 0.01f * z2;
        float z3 = nt0.w + e0.w + bb0.w; z3 = z3 > 0.f ? z3 : 0.01f * z3;
        psum  = vv0.x * z0;
        psum = fmaf(vv0.y, z1, psum);
        psum = fmaf(vv0.z, z2, psum);
        psum = fmaf(vv0.w, z3, psum);
        z0 = nt1.x + e1.x + bb1.x; z0 = z0 > 0.f ? z0 : 0.01f * z0;
        z1 = nt1.y + e1.y + bb1.y; z1 = z1 > 0.f ? z1 : 0.01f * z1;
        z2 = nt1.z + e1.z + bb1.z; z2 = z2 > 0.f ? z2 : 0.01f * z2;
        z3 = nt1.w + e1.w + bb1.w; z3 = z3 > 0.f ? z3 : 0.01f * z3;
        psum = fmaf(vv1.x, z0, psum);
        psum = fmaf(vv1.y, z1, psum);
        psum = fmaf(vv1.z, z2, psum);
        psum = fmaf(vv1.w, z3, psum);
    }
#pragma unroll
    for (int off = 4; off; off >>= 1)
        psum += __shfl_down_sync(0xffffffffu, psum, off);
    if (g == 0) s_pre[k] = psum;
    __syncthreads();

    if (tid < 32) {
        float pre = (tid < K_) ? s_pre[tid] + mval : -INFINITY;
        float w   = wval;
        float m1 = pre, m2 = w;
#pragma unroll
        for (int off = 8; off; off >>= 1) {
            m1 = fmaxf(m1, __shfl_xor_sync(0xffffffffu, m1, off));
            m2 = fmaxf(m2, __shfl_xor_sync(0xffffffffu, m2, off));
        }
        float e1v = (tid < K_) ? __expf(pre - m1) : 0.f;
        float e2v = (tid < K_) ? __expf(w   - m2) : 0.f;
        float s1 = e1v, s2 = e2v;
#pragma unroll
        for (int off = 8; off; off >>= 1) {
            s1 += __shfl_xor_sync(0xffffffffu, s1, off);
            s2 += __shfl_xor_sync(0xffffffffu, s2, off);
        }
        if (tid < K_) s_att[tid] = (e1v / s1) * (e2v / s2);
    }
    __syncthreads();

    float acc = 0.f;
#pragma unroll
    for (int kk = 0; kk < K_; kk++)
        acc = fmaf(s_att[kk], wv[kk], acc);
    g_temp[(size_t)n * D_ + tid] = acc;
}

// ---------------------------------------------------------------------------
// scatterE (levels 0,1): over compact winner list — write Wtmp row AND
// recompute g_E row. 16 winners / 256-thread block, grid = 1250, early exit.
// ---------------------------------------------------------------------------
__global__ void scatterE_kernel(float* __restrict__ Wtmp,
                                const int* __restrict__ nodes,
                                const float* __restrict__ W_att,
                                int level) {
    __shared__ __align__(16) float sWb[128 * 64];
    __shared__ __align__(16) float s_t[16 * 128];
    __shared__ int   s_n[16];
    __shared__ int   s_nd[16];

    int cnt = g_count[level];
    int base = blockIdx.x * 16;
    if (base >= cnt) return;
    int tid = threadIdx.x;

    for (int i = tid; i < 128 * 64; i += 256) {
        int d = i >> 6, a = i & 63;
        sWb[i] = W_att[(128 + d) * 64 + a];
    }
    if (tid < 16) {
        int item = base + tid;
        int nn = (item < cnt) ? g_list[level * N_ + item] : -1;
        s_n[tid]  = nn;
        s_nd[tid] = (nn >= 0) ? nodes[(size_t)level * N_ + nn] : -1;
    }
    __syncthreads();
    for (int i = tid; i < 512; i += 256) {
        int r = i >> 5, q = i & 31;
        int nn = s_n[r];
        float4 v = (nn >= 0)
            ? reinterpret_cast<const float4*>(g_temp + (size_t)nn * 128)[q]
            : make_float4(0.f, 0.f, 0.f, 0.f);
        reinterpret_cast<float4*>(s_t + r * 128)[q] = v;
        if (nn >= 0)
            reinterpret_cast<float4*>(Wtmp + (size_t)s_nd[r] * 128)[q] = v;
    }
    __syncthreads();

    int a  = tid & 63;
    int rg = tid >> 6;
    float acc[4] = {0.f, 0.f, 0.f, 0.f};
    const float* tr = s_t + (rg * 4) * 128;
#pragma unroll 4
    for (int d = 0; d < 128; d++) {
        float w = sWb[d * 64 + a];
        acc[0] = fmaf(tr[d],       w, acc[0]);
        acc[1] = fmaf(tr[128 + d], w, acc[1]);
        acc[2] = fmaf(tr[256 + d], w, acc[2]);
        acc[3] = fmaf(tr[384 + d], w, acc[3]);
    }
#pragma unroll
    for (int r = 0; r < 4; r++) {
        int nn = s_n[rg * 4 + r];
        if (nn >= 0)
            g_E[(size_t)s_nd[rg * 4 + r] * A_ + a] = acc[r];
    }
}

// ---------------------------------------------------------------------------
// scatter_copy (last level): row copy only, over compact list.
// ---------------------------------------------------------------------------
__global__ void scatter_copy_kernel(float* __restrict__ Wtmp,
                                    const int* __restrict__ nodes,
                                    int level) {
    int grp  = threadIdx.x >> 5;
    int lane = threadIdx.x & 31;
    int item = blockIdx.x * 8 + grp;
    if (item >= g_count[level]) return;
    int nn   = g_list[level * N_ + item];
    int node = nodes[(size_t)level * N_ + nn];
    reinterpret_cast<float4*>(Wtmp + (size_t)node * 128)[lane] =
        reinterpret_cast<const float4*>(g_temp + (size_t)nn * 128)[lane];
}

// ---------------------------------------------------------------------------
extern "C" void kernel_launch(void* const* d_in, const int* in_sizes, int n_in,
                              void* d_out, int out_size) {
    const float* Leaf_emb  = (const float*)d_in[0];
    const int*   nodes     = (const int*)  d_in[1];
    const int*   neighbors = (const int*)  d_in[2];
    const float* masks     = (const float*)d_in[3];
    const float* weights   = (const float*)d_in[4];
    const float* W_att     = (const float*)d_in[5];
    const float* b_att     = (const float*)d_in[6];
    const float* v_att     = (const float*)d_in[7];
    float* Wtmp = (float*)d_out;

    init_kernel<<<(L_ * V_ + 255) / 256, 256>>>();
    win_kernel <<<(L_ * N_ + 255) / 256, 256>>>(nodes);
    list_kernel<<<(L_ * N_ + 255) / 256, 256>>>(nodes);

    proj_kernel<<<V_ / 32, 256>>>(Leaf_emb, W_att, Wtmp);

    for (int lvl = 0; lvl < L_; lvl++) {
        attn_kernel<<<N_, 128>>>(Wtmp, nodes, neighbors, masks, weights,
                                 b_att, v_att, lvl);
        if (lvl < L_ - 1)
            scatterE_kernel<<<(N_ + 15) / 16, 256>>>(Wtmp, nodes, W_att, lvl);
        else
            scatter_copy_kernel<<<(N_ + 7) / 8, 256>>>(Wtmp, nodes, lvl);
    }
}